// round 6
// baseline (speedup 1.0000x reference)
#include <cuda_runtime.h>

using ull = unsigned long long;

#define R 3

// ---------------- f32x2 packed-math helpers (Blackwell FFMA2 path) ----------------

__device__ __forceinline__ ull ffma2(ull a, ull b, ull c) {
    ull d;
    asm("fma.rn.f32x2 %0, %1, %2, %3;" : "=l"(d) : "l"(a), "l"(b), "l"(c));
    return d;
}
__device__ __forceinline__ ull pk2(float x, float y) {
    ull r;
    asm("mov.b64 %0, {%1, %2};" : "=l"(r) : "f"(x), "f"(y));
    return r;
}
__device__ __forceinline__ void unpk2(ull v, float& x, float& y) {
    asm("mov.b64 {%0, %1}, %2;" : "=f"(x), "=f"(y) : "l"(v));
}
__device__ __forceinline__ float tanh_fast(float x) {
    float y;
    asm("tanh.approx.f32 %0, %1;" : "=f"(y) : "f"(x));
    return y;
}

// ---------------- shared-memory weight cache (masks + interleave baked) ----------------

struct __align__(16) Smem {
    float W1[4 * 64];
    float B1[64];
    float W2[64 * 32];
    float B2[32];
    float W3[32 * 8];
    float B3[8];
    float Pj[16];          // proj: interleaved {w[i][0], w[i][1]} pairs
    float Pc[8];           // proj: w[i][2]
    float Fh[10 * 64];     // flow hidden: [l][input(2)][32], input-1 row mask-baked
    float Fbh[10 * 32];
    float FoA[10 * 32];    // per layer 16 pairs: {wmu1[2j], wa1[2j]} (even units; odd masked to 0)
    float FoB[10 * 64];    // per layer 32 pairs: {wmu2[k], wa2[k]} (all units)
    float Fb[10 * 6 + 4];  // [l] = {bmu0, exp(-tanh(ba0)), bmu1, ba1, bmu2, ba2}
    float Pb[4];
};

__global__ __launch_bounds__(128, 4)
void gsi_kernel(const float* __restrict__ states,
                const float* __restrict__ enc_w1, const float* __restrict__ enc_b1,
                const float* __restrict__ enc_w2, const float* __restrict__ enc_b2,
                const float* __restrict__ enc_w3, const float* __restrict__ enc_b3,
                const float* __restrict__ proj_w, const float* __restrict__ proj_b,
                const float* __restrict__ flow_wh, const float* __restrict__ flow_bh,
                const float* __restrict__ flow_wmu, const float* __restrict__ flow_bmu,
                const float* __restrict__ flow_wa, const float* __restrict__ flow_ba,
                float* __restrict__ out, int B) {
    __shared__ Smem sm;
    const int tid = threadIdx.x;

    // ---- cooperative weight load + mask/interleave bake ----
    for (int i = tid; i < 4 * 64; i += 128)  sm.W1[i] = enc_w1[i];
    for (int i = tid; i < 64;     i += 128)  sm.B1[i] = enc_b1[i];
    for (int i = tid; i < 64 * 32; i += 128) sm.W2[i] = enc_w2[i];
    for (int i = tid; i < 32;     i += 128)  sm.B2[i] = enc_b2[i];
    for (int i = tid; i < 32 * 8; i += 128)  sm.W3[i] = enc_w3[i];
    for (int i = tid; i < 8;      i += 128)  sm.B3[i] = enc_b3[i];
    if (tid < 8) {
        sm.Pj[2 * tid]     = proj_w[tid * 3 + 0];
        sm.Pj[2 * tid + 1] = proj_w[tid * 3 + 1];
        sm.Pc[tid]         = proj_w[tid * 3 + 2];
    }
    if (tid < 3) sm.Pb[tid] = proj_b[tid];
    if (tid == 3) sm.Pb[3] = 0.f;
    // flow hidden: m_h[0][j]=1 all j; m_h[1][j]=1 iff j odd; m_h[2][:]=0 (dropped)
    for (int i = tid; i < 10 * 32; i += 128) {
        int l = i >> 5, j = i & 31;
        sm.Fh[l * 64 + j]      = flow_wh[l * 96 + j];
        sm.Fh[l * 64 + 32 + j] = (j & 1) ? flow_wh[l * 96 + 32 + j] : 0.f;
        sm.Fbh[i] = flow_bh[i];
    }
    // flow output: m_o[k][1]=1 iff k even; m_o[k][2]=1; m_o[k][0]=0 (out0 = pure bias)
    for (int i = tid; i < 10 * 16; i += 128) {
        int l = i >> 4, j = i & 15;
        int base = l * 96 + (2 * j) * 3;
        sm.FoA[l * 32 + 2 * j]     = flow_wmu[base + 1];
        sm.FoA[l * 32 + 2 * j + 1] = flow_wa[base + 1];
    }
    for (int i = tid; i < 10 * 32; i += 128) {
        int l = i >> 5, k = i & 31;
        int base = l * 96 + k * 3;
        sm.FoB[l * 64 + 2 * k]     = flow_wmu[base + 2];
        sm.FoB[l * 64 + 2 * k + 1] = flow_wa[base + 2];
    }
    if (tid < 10) {
        int l = tid;
        sm.Fb[l * 6 + 0] = flow_bmu[l * 3 + 0];
        sm.Fb[l * 6 + 1] = expf(-tanhf(flow_ba[l * 3 + 0]));
        sm.Fb[l * 6 + 2] = flow_bmu[l * 3 + 1];
        sm.Fb[l * 6 + 3] = flow_ba[l * 3 + 1];
        sm.Fb[l * 6 + 4] = flow_bmu[l * 3 + 2];
        sm.Fb[l * 6 + 5] = flow_ba[l * 3 + 2];
    }
    __syncthreads();

    const int rbase = blockIdx.x * (128 * R) + tid;

    ull xp[R][4];
#pragma unroll
    for (int q = 0; q < R; q++) {
        int rl = rbase + q * 128;
        if (rl > B - 1) rl = B - 1;                      // clamp: safe load, store guarded later
        float4 sv = reinterpret_cast<const float4*>(states)[rl];
        xp[q][0] = pk2(sv.x, sv.x); xp[q][1] = pk2(sv.y, sv.y);
        xp[q][2] = pk2(sv.z, sv.z); xp[q][3] = pk2(sv.w, sv.w);
    }

    // ---- encoder: two passes over h2 halves (16 units each) to cap register peak ----
    // enc3 accumulators live across both passes.
    ull cp[R][4];
    {
        const ulonglong2* pb = reinterpret_cast<const ulonglong2*>(sm.B3);
        ulonglong2 v0b = pb[0], v1b = pb[1];
#pragma unroll
        for (int q = 0; q < R; q++) {
            cp[q][0] = v0b.x; cp[q][1] = v0b.y; cp[q][2] = v1b.x; cp[q][3] = v1b.y;
        }
    }

#pragma unroll 1
    for (int half = 0; half < 2; half++) {
        // h2 half: 16 units = 8 ulls per row
        ull h2h[R][8];
        {
            const ulonglong2* pb = reinterpret_cast<const ulonglong2*>(sm.B2 + half * 16);
#pragma unroll
            for (int p = 0; p < 4; p++) {
                ulonglong2 v = pb[p];
#pragma unroll
                for (int q = 0; q < R; q++) { h2h[q][2 * p] = v.x; h2h[q][2 * p + 1] = v.y; }
            }
        }
        // sweep all 64 h1 units in chunks of 8 (recomputed per half; enc1 is cheap)
#pragma unroll 1
        for (int c = 0; c < 8; c++) {
            ull h1[R][4];
            const ulonglong2* pb1 = reinterpret_cast<const ulonglong2*>(sm.B1 + c * 8);
#pragma unroll
            for (int p = 0; p < 2; p++) {
                ulonglong2 v = pb1[p];
#pragma unroll
                for (int q = 0; q < R; q++) { h1[q][2 * p] = v.x; h1[q][2 * p + 1] = v.y; }
            }
#pragma unroll
            for (int i = 0; i < 4; i++) {
                const ulonglong2* w = reinterpret_cast<const ulonglong2*>(sm.W1 + i * 64 + c * 8);
#pragma unroll
                for (int p = 0; p < 2; p++) {
                    ulonglong2 v = w[p];
#pragma unroll
                    for (int q = 0; q < R; q++) {
                        h1[q][2 * p]     = ffma2(xp[q][i], v.x, h1[q][2 * p]);
                        h1[q][2 * p + 1] = ffma2(xp[q][i], v.y, h1[q][2 * p + 1]);
                    }
                }
            }
            // consume chunk into h2 half
#pragma unroll
            for (int j = 0; j < 4; j++) {
                ull ab[R], bb[R];
#pragma unroll
                for (int q = 0; q < R; q++) {
                    float a, b;
                    unpk2(h1[q][j], a, b);
                    a = fmaxf(a, 0.f); b = fmaxf(b, 0.f);
                    ab[q] = pk2(a, a); bb[q] = pk2(b, b);
                }
                const int u = c * 8 + 2 * j;
                const ulonglong2* wa = reinterpret_cast<const ulonglong2*>(sm.W2 + u * 32 + half * 16);
                const ulonglong2* wb = reinterpret_cast<const ulonglong2*>(sm.W2 + u * 32 + 32 + half * 16);
#pragma unroll
                for (int p = 0; p < 4; p++) {
                    ulonglong2 v = wa[p];
#pragma unroll
                    for (int q = 0; q < R; q++) {
                        h2h[q][2 * p]     = ffma2(ab[q], v.x, h2h[q][2 * p]);
                        h2h[q][2 * p + 1] = ffma2(ab[q], v.y, h2h[q][2 * p + 1]);
                    }
                }
#pragma unroll
                for (int p = 0; p < 4; p++) {
                    ulonglong2 v = wb[p];
#pragma unroll
                    for (int q = 0; q < R; q++) {
                        h2h[q][2 * p]     = ffma2(bb[q], v.x, h2h[q][2 * p]);
                        h2h[q][2 * p + 1] = ffma2(bb[q], v.y, h2h[q][2 * p + 1]);
                    }
                }
            }
        }
        // ---- consume h2 half into enc3 accumulators ----
#pragma unroll
        for (int j = 0; j < 8; j++) {
            ull ab[R], bb[R];
#pragma unroll
            for (int q = 0; q < R; q++) {
                float a, b;
                unpk2(h2h[q][j], a, b);
                a = fmaxf(a, 0.f); b = fmaxf(b, 0.f);
                ab[q] = pk2(a, a); bb[q] = pk2(b, b);
            }
            const int u = half * 16 + 2 * j;
            const ulonglong2* wa = reinterpret_cast<const ulonglong2*>(sm.W3 + u * 8);
            const ulonglong2* wb = reinterpret_cast<const ulonglong2*>(sm.W3 + u * 8 + 8);
            ulonglong2 va0 = wa[0], va1 = wa[1];
            ulonglong2 vb0 = wb[0], vb1 = wb[1];
#pragma unroll
            for (int q = 0; q < R; q++) {
                cp[q][0] = ffma2(ab[q], va0.x, cp[q][0]); cp[q][1] = ffma2(ab[q], va0.y, cp[q][1]);
                cp[q][2] = ffma2(ab[q], va1.x, cp[q][2]); cp[q][3] = ffma2(ab[q], va1.y, cp[q][3]);
                cp[q][0] = ffma2(bb[q], vb0.x, cp[q][0]); cp[q][1] = ffma2(bb[q], vb0.y, cp[q][1]);
                cp[q][2] = ffma2(bb[q], vb1.x, cp[q][2]); cp[q][3] = ffma2(bb[q], vb1.y, cp[q][3]);
            }
        }
    }

    // ---- projection 8 -> 3 ----
    ull a01[R];
    float x2[R], x0[R], x1[R];
#pragma unroll
    for (int q = 0; q < R; q++) { a01[q] = pk2(sm.Pb[0], sm.Pb[1]); x2[q] = sm.Pb[2]; }
#pragma unroll
    for (int jj = 0; jj < 4; jj++) {
        ull w0 = reinterpret_cast<const ull*>(sm.Pj)[2 * jj];
        ull w1 = reinterpret_cast<const ull*>(sm.Pj)[2 * jj + 1];
        float pc0 = sm.Pc[2 * jj], pc1 = sm.Pc[2 * jj + 1];
#pragma unroll
        for (int q = 0; q < R; q++) {
            float cc0, cc1;
            unpk2(cp[q][jj], cc0, cc1);
            a01[q] = ffma2(pk2(cc0, cc0), w0, a01[q]);
            a01[q] = ffma2(pk2(cc1, cc1), w1, a01[q]);
            x2[q] = fmaf(cc0, pc0, x2[q]);
            x2[q] = fmaf(cc1, pc1, x2[q]);
        }
    }
#pragma unroll
    for (int q = 0; q < R; q++) unpk2(a01[q], x0[q], x1[q]);

    // ---- MAF flow: 10 masked affine-AR layers + flip, hidden in 2 chunks of 16 ----
#pragma unroll 1
    for (int l = 0; l < 10; l++) {
        const float* fh  = sm.Fh  + l * 64;
        const float* fbh = sm.Fbh + l * 32;
        const float* foA = sm.FoA + l * 32;
        const float* foB = sm.FoB + l * 64;
        const float* fb  = sm.Fb  + l * 6;

        ull x0b[R], x1b[R];
#pragma unroll
        for (int q = 0; q < R; q++) { x0b[q] = pk2(x0[q], x0[q]); x1b[q] = pk2(x1[q], x1[q]); }

        ull acc1[R], acc2[R];
#pragma unroll
        for (int q = 0; q < R; q++) {
            acc1[q] = pk2(fb[2], fb[3]);
            acc2[q] = pk2(fb[4], fb[5]);
        }

#pragma unroll
        for (int ch = 0; ch < 2; ch++) {
            ull hh[R][8];
            const ulonglong2* pbh = reinterpret_cast<const ulonglong2*>(fbh + ch * 16);
#pragma unroll
            for (int p = 0; p < 4; p++) {
                ulonglong2 v = pbh[p];
#pragma unroll
                for (int q = 0; q < R; q++) { hh[q][2 * p] = v.x; hh[q][2 * p + 1] = v.y; }
            }
            const ulonglong2* w0 = reinterpret_cast<const ulonglong2*>(fh + ch * 16);
            const ulonglong2* w1 = reinterpret_cast<const ulonglong2*>(fh + 32 + ch * 16);
#pragma unroll
            for (int p = 0; p < 4; p++) {
                ulonglong2 v = w0[p];
#pragma unroll
                for (int q = 0; q < R; q++) {
                    hh[q][2 * p]     = ffma2(x0b[q], v.x, hh[q][2 * p]);
                    hh[q][2 * p + 1] = ffma2(x0b[q], v.y, hh[q][2 * p + 1]);
                }
            }
#pragma unroll
            for (int p = 0; p < 4; p++) {
                ulonglong2 v = w1[p];
#pragma unroll
                for (int q = 0; q < R; q++) {
                    hh[q][2 * p]     = ffma2(x1b[q], v.x, hh[q][2 * p]);
                    hh[q][2 * p + 1] = ffma2(x1b[q], v.y, hh[q][2 * p + 1]);
                }
            }
            // consume chunk into output accumulators
#pragma unroll
            for (int j = 0; j < 8; j++) {
                ull wv = reinterpret_cast<const ull*>(foA)[ch * 8 + j];
                ulonglong2 wv2 = reinterpret_cast<const ulonglong2*>(foB)[ch * 8 + j];
#pragma unroll
                for (int q = 0; q < R; q++) {
                    float a, b;
                    unpk2(hh[q][j], a, b);
                    a = fmaxf(a, 0.f); b = fmaxf(b, 0.f);
                    ull ab = pk2(a, a), bb = pk2(b, b);
                    acc1[q] = ffma2(ab, wv, acc1[q]);
                    acc2[q] = ffma2(ab, wv2.x, acc2[q]);
                    acc2[q] = ffma2(bb, wv2.y, acc2[q]);
                }
            }
        }

        float bmu0 = fb[0], esc0 = fb[1];
#pragma unroll
        for (int q = 0; q < R; q++) {
            float mu1, al1, mu2, al2;
            unpk2(acc1[q], mu1, al1); unpk2(acc2[q], mu2, al2);
            float t1 = tanh_fast(al1);                 // HW MUFU.TANH
            float t2 = tanh_fast(al2);
            float nx0 = (x0[q] - bmu0) * esc0;
            float nx1 = (x1[q] - mu1) * __expf(-t1);
            float nx2 = (x2[q] - mu2) * __expf(-t2);
            x0[q] = nx2; x1[q] = nx1; x2[q] = nx0;
        }
    }

    // ---- squash + HSV + store  (sigmoid(x) = 0.5*(1+tanh(x/2))) ----
#pragma unroll
    for (int q = 0; q < R; q++) {
        int rq = rbase + q * 128;
        if (rq < B) {
            float t0 = tanh_fast(0.5f * x0[q]);
            float t1 = tanh_fast(0.5f * x1[q]);
            float t2 = tanh_fast(0.5f * x2[q]);
            out[3 * rq + 0] = fmaf(3.14159265358979323846f, t0, 3.14159265358979323846f);
            out[3 * rq + 1] = fmaf(0.5f, t1, 0.5f);
            out[3 * rq + 2] = fmaf(0.5f, t2, 0.5f);
        }
    }
}

extern "C" void kernel_launch(void* const* d_in, const int* in_sizes, int n_in,
                              void* d_out, int out_size) {
    (void)n_in; (void)out_size;
    const float* states   = (const float*)d_in[0];
    const float* enc_w1   = (const float*)d_in[1];
    const float* enc_b1   = (const float*)d_in[2];
    const float* enc_w2   = (const float*)d_in[3];
    const float* enc_b2   = (const float*)d_in[4];
    const float* enc_w3   = (const float*)d_in[5];
    const float* enc_b3   = (const float*)d_in[6];
    const float* proj_w   = (const float*)d_in[7];
    const float* proj_b   = (const float*)d_in[8];
    const float* flow_wh  = (const float*)d_in[9];
    const float* flow_bh  = (const float*)d_in[10];
    const float* flow_wmu = (const float*)d_in[11];
    const float* flow_bmu = (const float*)d_in[12];
    const float* flow_wa  = (const float*)d_in[13];
    const float* flow_ba  = (const float*)d_in[14];

    const int B = in_sizes[0] / 4;
    const int grid = (B + 128 * R - 1) / (128 * R);
    gsi_kernel<<<grid, 128>>>(states, enc_w1, enc_b1, enc_w2, enc_b2, enc_w3, enc_b3,
                              proj_w, proj_b, flow_wh, flow_bh, flow_wmu, flow_bmu,
                              flow_wa, flow_ba, (float*)d_out, B);
}

// round 7
// speedup vs baseline: 1.0967x; 1.0967x over previous
#include <cuda_runtime.h>

using ull = unsigned long long;

#define R 3

// ---------------- f32x2 packed-math helpers (Blackwell FFMA2 path) ----------------

__device__ __forceinline__ ull ffma2(ull a, ull b, ull c) {
    ull d;
    asm("fma.rn.f32x2 %0, %1, %2, %3;" : "=l"(d) : "l"(a), "l"(b), "l"(c));
    return d;
}
__device__ __forceinline__ ull pk2(float x, float y) {
    ull r;
    asm("mov.b64 %0, {%1, %2};" : "=l"(r) : "f"(x), "f"(y));
    return r;
}
__device__ __forceinline__ void unpk2(ull v, float& x, float& y) {
    asm("mov.b64 {%0, %1}, %2;" : "=f"(x), "=f"(y) : "l"(v));
}
__device__ __forceinline__ float tanh_fast(float x) {
    float y;
    asm("tanh.approx.f32 %0, %1;" : "=f"(y) : "f"(x));
    return y;
}

// ---------------- shared-memory weight cache ----------------
// Flow hidden units are PERMUTED: new index n<16 -> orig unit 2n+1 (degree-2, "odd"),
// n>=16 -> orig unit 2(n-16) (degree-1, "even"). Consequences:
//   x1 feeds ONLY block1 (n<16);  acc1 (mu1/alpha1) fed ONLY by block2 units.
struct __align__(16) Smem {
    float W1[4 * 64];
    float B1[64];
    float W2[64 * 32];
    float B2[32];
    float W3[32 * 8];
    float B3[8];
    float Pj[16];           // proj: interleaved {w[i][0], w[i][1]} pairs
    float Pc[8];            // proj: w[i][2]
    float FhX0[10 * 32];    // x0 weights, reordered units
    float FhX1[10 * 16];    // x1 weights, block1 units only
    float Fbh[10 * 32];     // hidden bias, reordered
    float FoB[10 * 64];     // per new-unit pair {wmu2[u], wa2[u]}  (ull index = new unit)
    float FoA2[10 * 32];    // block2 units only: {wmu1[u], wa1[u]} (ull index = n_e = newidx-16)
    float Fb[10 * 6 + 4];   // [l] = {bmu0, exp(-tanh(ba0)), bmu1, ba1, bmu2, ba2}
    float Pb[4];
};

__global__ __launch_bounds__(128, 3)
void gsi_kernel(const float* __restrict__ states,
                const float* __restrict__ enc_w1, const float* __restrict__ enc_b1,
                const float* __restrict__ enc_w2, const float* __restrict__ enc_b2,
                const float* __restrict__ enc_w3, const float* __restrict__ enc_b3,
                const float* __restrict__ proj_w, const float* __restrict__ proj_b,
                const float* __restrict__ flow_wh, const float* __restrict__ flow_bh,
                const float* __restrict__ flow_wmu, const float* __restrict__ flow_bmu,
                const float* __restrict__ flow_wa, const float* __restrict__ flow_ba,
                float* __restrict__ out, int B) {
    __shared__ Smem sm;
    const int tid = threadIdx.x;

    // ---- cooperative weight load + mask/permute bake ----
    for (int i = tid; i < 4 * 64; i += 128)  sm.W1[i] = enc_w1[i];
    for (int i = tid; i < 64;     i += 128)  sm.B1[i] = enc_b1[i];
    for (int i = tid; i < 64 * 32; i += 128) sm.W2[i] = enc_w2[i];
    for (int i = tid; i < 32;     i += 128)  sm.B2[i] = enc_b2[i];
    for (int i = tid; i < 32 * 8; i += 128)  sm.W3[i] = enc_w3[i];
    for (int i = tid; i < 8;      i += 128)  sm.B3[i] = enc_b3[i];
    if (tid < 8) {
        sm.Pj[2 * tid]     = proj_w[tid * 3 + 0];
        sm.Pj[2 * tid + 1] = proj_w[tid * 3 + 1];
        sm.Pc[tid]         = proj_w[tid * 3 + 2];
    }
    if (tid < 3) sm.Pb[tid] = proj_b[tid];
    if (tid == 3) sm.Pb[3] = 0.f;
    // flow bake with unit permutation (n<16: u=2n+1 deg2; n>=16: u=2(n-16) deg1)
    for (int i = tid; i < 10 * 16; i += 128) {
        int l = i >> 4, n = i & 15;
        int uo = 2 * n + 1, ue = 2 * n;
        const float* wh = flow_wh + l * 96;
        sm.FhX0[l * 32 + n]      = wh[uo];            // row 0 (input x0), mask all-ones
        sm.FhX0[l * 32 + 16 + n] = wh[ue];
        sm.FhX1[l * 16 + n]      = wh[32 + uo];       // row 1 (x1), only deg-2 units
        sm.Fbh[l * 32 + n]       = flow_bh[l * 32 + uo];
        sm.Fbh[l * 32 + 16 + n]  = flow_bh[l * 32 + ue];
        // output stage: wmu/wa column 2 ("x2" output) for all units
        sm.FoB[l * 64 + 2 * n]            = flow_wmu[l * 96 + uo * 3 + 2];
        sm.FoB[l * 64 + 2 * n + 1]        = flow_wa [l * 96 + uo * 3 + 2];
        sm.FoB[l * 64 + 2 * (16 + n)]     = flow_wmu[l * 96 + ue * 3 + 2];
        sm.FoB[l * 64 + 2 * (16 + n) + 1] = flow_wa [l * 96 + ue * 3 + 2];
        // column 1 ("x1" output): only deg-1 (even) units contribute
        sm.FoA2[l * 32 + 2 * n]     = flow_wmu[l * 96 + ue * 3 + 1];
        sm.FoA2[l * 32 + 2 * n + 1] = flow_wa [l * 96 + ue * 3 + 1];
    }
    if (tid < 10) {
        int l = tid;
        sm.Fb[l * 6 + 0] = flow_bmu[l * 3 + 0];
        sm.Fb[l * 6 + 1] = expf(-tanhf(flow_ba[l * 3 + 0]));
        sm.Fb[l * 6 + 2] = flow_bmu[l * 3 + 1];
        sm.Fb[l * 6 + 3] = flow_ba[l * 3 + 1];
        sm.Fb[l * 6 + 4] = flow_bmu[l * 3 + 2];
        sm.Fb[l * 6 + 5] = flow_ba[l * 3 + 2];
    }
    __syncthreads();

    const int rbase = blockIdx.x * (128 * R) + tid;

    ull xp[R][4];
#pragma unroll
    for (int q = 0; q < R; q++) {
        int rl = rbase + q * 128;
        if (rl > B - 1) rl = B - 1;                      // clamp load; store guarded later
        float4 sv = reinterpret_cast<const float4*>(states)[rl];
        xp[q][0] = pk2(sv.x, sv.x); xp[q][1] = pk2(sv.y, sv.y);
        xp[q][2] = pk2(sv.z, sv.z); xp[q][3] = pk2(sv.w, sv.w);
    }

    // ---- fused enc1 (4->64) + enc2 (64->32), single pass, h1 chunked by 8 ----
    ull h2[R][16];
    {
        const ulonglong2* pb = reinterpret_cast<const ulonglong2*>(sm.B2);
#pragma unroll
        for (int p = 0; p < 8; p++) {
            ulonglong2 v = pb[p];
#pragma unroll
            for (int q = 0; q < R; q++) { h2[q][2 * p] = v.x; h2[q][2 * p + 1] = v.y; }
        }
    }
#pragma unroll 1
    for (int c = 0; c < 8; c++) {
        ull h1[R][4];
        const ulonglong2* pb1 = reinterpret_cast<const ulonglong2*>(sm.B1 + c * 8);
#pragma unroll
        for (int p = 0; p < 2; p++) {
            ulonglong2 v = pb1[p];
#pragma unroll
            for (int q = 0; q < R; q++) { h1[q][2 * p] = v.x; h1[q][2 * p + 1] = v.y; }
        }
#pragma unroll
        for (int i = 0; i < 4; i++) {
            const ulonglong2* w = reinterpret_cast<const ulonglong2*>(sm.W1 + i * 64 + c * 8);
#pragma unroll
            for (int p = 0; p < 2; p++) {
                ulonglong2 v = w[p];
#pragma unroll
                for (int q = 0; q < R; q++) {
                    h1[q][2 * p]     = ffma2(xp[q][i], v.x, h1[q][2 * p]);
                    h1[q][2 * p + 1] = ffma2(xp[q][i], v.y, h1[q][2 * p + 1]);
                }
            }
        }
#pragma unroll
        for (int j = 0; j < 4; j++) {
            ull ab[R], bb[R];
#pragma unroll
            for (int q = 0; q < R; q++) {
                float a, b;
                unpk2(h1[q][j], a, b);
                a = fmaxf(a, 0.f); b = fmaxf(b, 0.f);
                ab[q] = pk2(a, a); bb[q] = pk2(b, b);
            }
            const int u = c * 8 + 2 * j;
            const ulonglong2* wa = reinterpret_cast<const ulonglong2*>(sm.W2 + u * 32);
            const ulonglong2* wb = reinterpret_cast<const ulonglong2*>(sm.W2 + u * 32 + 32);
#pragma unroll
            for (int p = 0; p < 8; p++) {
                ulonglong2 v = wa[p];
#pragma unroll
                for (int q = 0; q < R; q++) {
                    h2[q][2 * p]     = ffma2(ab[q], v.x, h2[q][2 * p]);
                    h2[q][2 * p + 1] = ffma2(ab[q], v.y, h2[q][2 * p + 1]);
                }
            }
#pragma unroll
            for (int p = 0; p < 8; p++) {
                ulonglong2 v = wb[p];
#pragma unroll
                for (int q = 0; q < R; q++) {
                    h2[q][2 * p]     = ffma2(bb[q], v.x, h2[q][2 * p]);
                    h2[q][2 * p + 1] = ffma2(bb[q], v.y, h2[q][2 * p + 1]);
                }
            }
        }
    }

    // ---- enc3: 32 -> 8 ----
    ull cp[R][4];
    {
        const ulonglong2* pb = reinterpret_cast<const ulonglong2*>(sm.B3);
        ulonglong2 v0b = pb[0], v1b = pb[1];
#pragma unroll
        for (int q = 0; q < R; q++) {
            cp[q][0] = v0b.x; cp[q][1] = v0b.y; cp[q][2] = v1b.x; cp[q][3] = v1b.y;
        }
    }
#pragma unroll
    for (int j = 0; j < 16; j++) {
        ull ab[R], bb[R];
#pragma unroll
        for (int q = 0; q < R; q++) {
            float a, b;
            unpk2(h2[q][j], a, b);
            a = fmaxf(a, 0.f); b = fmaxf(b, 0.f);
            ab[q] = pk2(a, a); bb[q] = pk2(b, b);
        }
        const ulonglong2* wa = reinterpret_cast<const ulonglong2*>(sm.W3 + (2 * j) * 8);
        const ulonglong2* wb = reinterpret_cast<const ulonglong2*>(sm.W3 + (2 * j) * 8 + 8);
        ulonglong2 va0 = wa[0], va1 = wa[1];
        ulonglong2 vb0 = wb[0], vb1 = wb[1];
#pragma unroll
        for (int q = 0; q < R; q++) {
            cp[q][0] = ffma2(ab[q], va0.x, cp[q][0]); cp[q][1] = ffma2(ab[q], va0.y, cp[q][1]);
            cp[q][2] = ffma2(ab[q], va1.x, cp[q][2]); cp[q][3] = ffma2(ab[q], va1.y, cp[q][3]);
            cp[q][0] = ffma2(bb[q], vb0.x, cp[q][0]); cp[q][1] = ffma2(bb[q], vb0.y, cp[q][1]);
            cp[q][2] = ffma2(bb[q], vb1.x, cp[q][2]); cp[q][3] = ffma2(bb[q], vb1.y, cp[q][3]);
        }
    }

    // ---- projection 8 -> 3 ----
    ull a01[R];
    float x2[R], x0[R], x1[R];
#pragma unroll
    for (int q = 0; q < R; q++) { a01[q] = pk2(sm.Pb[0], sm.Pb[1]); x2[q] = sm.Pb[2]; }
#pragma unroll
    for (int jj = 0; jj < 4; jj++) {
        ull w0 = reinterpret_cast<const ull*>(sm.Pj)[2 * jj];
        ull w1 = reinterpret_cast<const ull*>(sm.Pj)[2 * jj + 1];
        float pc0 = sm.Pc[2 * jj], pc1 = sm.Pc[2 * jj + 1];
#pragma unroll
        for (int q = 0; q < R; q++) {
            float cc0, cc1;
            unpk2(cp[q][jj], cc0, cc1);
            a01[q] = ffma2(pk2(cc0, cc0), w0, a01[q]);
            a01[q] = ffma2(pk2(cc1, cc1), w1, a01[q]);
            x2[q] = fmaf(cc0, pc0, x2[q]);
            x2[q] = fmaf(cc1, pc1, x2[q]);
        }
    }
#pragma unroll
    for (int q = 0; q < R; q++) unpk2(a01[q], x0[q], x1[q]);

    // ---- MAF flow: 10 layers, units permuted (block1: deg2, block2: deg1) ----
#pragma unroll 1
    for (int l = 0; l < 10; l++) {
        const float* fhx0 = sm.FhX0 + l * 32;
        const float* fhx1 = sm.FhX1 + l * 16;
        const float* fbh  = sm.Fbh  + l * 32;
        const float* foB  = sm.FoB  + l * 64;
        const float* foA2 = sm.FoA2 + l * 32;
        const float* fb   = sm.Fb   + l * 6;

        ull x0b[R], x1b[R];
#pragma unroll
        for (int q = 0; q < R; q++) { x0b[q] = pk2(x0[q], x0[q]); x1b[q] = pk2(x1[q], x1[q]); }

        ull acc1[R], acc2[R];
#pragma unroll
        for (int q = 0; q < R; q++) {
            acc1[q] = pk2(fb[2], fb[3]);
            acc2[q] = pk2(fb[4], fb[5]);
        }

        // ---- block1: 16 deg-2 units (receive x0 AND x1; feed acc2 only) ----
        {
            ull hh[R][8];
            const ulonglong2* pbh = reinterpret_cast<const ulonglong2*>(fbh);
#pragma unroll
            for (int p = 0; p < 4; p++) {
                ulonglong2 v = pbh[p];
#pragma unroll
                for (int q = 0; q < R; q++) { hh[q][2 * p] = v.x; hh[q][2 * p + 1] = v.y; }
            }
            const ulonglong2* w0 = reinterpret_cast<const ulonglong2*>(fhx0);
            const ulonglong2* w1 = reinterpret_cast<const ulonglong2*>(fhx1);
#pragma unroll
            for (int p = 0; p < 4; p++) {
                ulonglong2 v = w0[p];
#pragma unroll
                for (int q = 0; q < R; q++) {
                    hh[q][2 * p]     = ffma2(x0b[q], v.x, hh[q][2 * p]);
                    hh[q][2 * p + 1] = ffma2(x0b[q], v.y, hh[q][2 * p + 1]);
                }
            }
#pragma unroll
            for (int p = 0; p < 4; p++) {
                ulonglong2 v = w1[p];
#pragma unroll
                for (int q = 0; q < R; q++) {
                    hh[q][2 * p]     = ffma2(x1b[q], v.x, hh[q][2 * p]);
                    hh[q][2 * p + 1] = ffma2(x1b[q], v.y, hh[q][2 * p + 1]);
                }
            }
#pragma unroll
            for (int j = 0; j < 8; j++) {
                ulonglong2 wv2 = reinterpret_cast<const ulonglong2*>(foB)[j];
#pragma unroll
                for (int q = 0; q < R; q++) {
                    float a, b;
                    unpk2(hh[q][j], a, b);
                    a = fmaxf(a, 0.f); b = fmaxf(b, 0.f);
                    acc2[q] = ffma2(pk2(a, a), wv2.x, acc2[q]);
                    acc2[q] = ffma2(pk2(b, b), wv2.y, acc2[q]);
                }
            }
        }
        // ---- block2: 16 deg-1 units (receive x0 only; feed acc1 AND acc2) ----
        {
            ull hh[R][8];
            const ulonglong2* pbh = reinterpret_cast<const ulonglong2*>(fbh + 16);
#pragma unroll
            for (int p = 0; p < 4; p++) {
                ulonglong2 v = pbh[p];
#pragma unroll
                for (int q = 0; q < R; q++) { hh[q][2 * p] = v.x; hh[q][2 * p + 1] = v.y; }
            }
            const ulonglong2* w0 = reinterpret_cast<const ulonglong2*>(fhx0 + 16);
#pragma unroll
            for (int p = 0; p < 4; p++) {
                ulonglong2 v = w0[p];
#pragma unroll
                for (int q = 0; q < R; q++) {
                    hh[q][2 * p]     = ffma2(x0b[q], v.x, hh[q][2 * p]);
                    hh[q][2 * p + 1] = ffma2(x0b[q], v.y, hh[q][2 * p + 1]);
                }
            }
#pragma unroll
            for (int j = 0; j < 8; j++) {
                ulonglong2 wv2 = reinterpret_cast<const ulonglong2*>(foB)[8 + j];
                ulonglong2 wv1 = reinterpret_cast<const ulonglong2*>(foA2)[j];
#pragma unroll
                for (int q = 0; q < R; q++) {
                    float a, b;
                    unpk2(hh[q][j], a, b);
                    a = fmaxf(a, 0.f); b = fmaxf(b, 0.f);
                    ull ab = pk2(a, a), bb = pk2(b, b);
                    acc2[q] = ffma2(ab, wv2.x, acc2[q]);
                    acc2[q] = ffma2(bb, wv2.y, acc2[q]);
                    acc1[q] = ffma2(ab, wv1.x, acc1[q]);
                    acc1[q] = ffma2(bb, wv1.y, acc1[q]);
                }
            }
        }

        float bmu0 = fb[0], esc0 = fb[1];
#pragma unroll
        for (int q = 0; q < R; q++) {
            float mu1, al1, mu2, al2;
            unpk2(acc1[q], mu1, al1); unpk2(acc2[q], mu2, al2);
            float t1 = tanh_fast(al1);
            float t2 = tanh_fast(al2);
            float nx0 = (x0[q] - bmu0) * esc0;
            float nx1 = (x1[q] - mu1) * __expf(-t1);
            float nx2 = (x2[q] - mu2) * __expf(-t2);
            x0[q] = nx2; x1[q] = nx1; x2[q] = nx0;
        }
    }

    // ---- squash + HSV + store  (sigmoid(x) = 0.5*(1+tanh(x/2))) ----
#pragma unroll
    for (int q = 0; q < R; q++) {
        int rq = rbase + q * 128;
        if (rq < B) {
            float t0 = tanh_fast(0.5f * x0[q]);
            float t1 = tanh_fast(0.5f * x1[q]);
            float t2 = tanh_fast(0.5f * x2[q]);
            out[3 * rq + 0] = fmaf(3.14159265358979323846f, t0, 3.14159265358979323846f);
            out[3 * rq + 1] = fmaf(0.5f, t1, 0.5f);
            out[3 * rq + 2] = fmaf(0.5f, t2, 0.5f);
        }
    }
}

extern "C" void kernel_launch(void* const* d_in, const int* in_sizes, int n_in,
                              void* d_out, int out_size) {
    (void)n_in; (void)out_size;
    const float* states   = (const float*)d_in[0];
    const float* enc_w1   = (const float*)d_in[1];
    const float* enc_b1   = (const float*)d_in[2];
    const float* enc_w2   = (const float*)d_in[3];
    const float* enc_b2   = (const float*)d_in[4];
    const float* enc_w3   = (const float*)d_in[5];
    const float* enc_b3   = (const float*)d_in[6];
    const float* proj_w   = (const float*)d_in[7];
    const float* proj_b   = (const float*)d_in[8];
    const float* flow_wh  = (const float*)d_in[9];
    const float* flow_bh  = (const float*)d_in[10];
    const float* flow_wmu = (const float*)d_in[11];
    const float* flow_bmu = (const float*)d_in[12];
    const float* flow_wa  = (const float*)d_in[13];
    const float* flow_ba  = (const float*)d_in[14];

    const int B = in_sizes[0] / 4;
    const int grid = (B + 128 * R - 1) / (128 * R);
    gsi_kernel<<<grid, 128>>>(states, enc_w1, enc_b1, enc_w2, enc_b2, enc_w3, enc_b3,
                              proj_w, proj_b, flow_wh, flow_bh, flow_wmu, flow_bmu,
                              flow_wa, flow_ba, (float*)d_out, B);
}

// round 9
// speedup vs baseline: 1.1216x; 1.0227x over previous
#include <cuda_runtime.h>

using ull = unsigned long long;

#define R 3

// ---------------- f32x2 packed-math helpers (Blackwell FFMA2 path) ----------------

__device__ __forceinline__ ull ffma2(ull a, ull b, ull c) {
    ull d;
    asm("fma.rn.f32x2 %0, %1, %2, %3;" : "=l"(d) : "l"(a), "l"(b), "l"(c));
    return d;
}
__device__ __forceinline__ ull pk2(float x, float y) {
    ull r;
    asm("mov.b64 %0, {%1, %2};" : "=l"(r) : "f"(x), "f"(y));
    return r;
}
__device__ __forceinline__ void unpk2(ull v, float& x, float& y) {
    asm("mov.b64 {%0, %1}, %2;" : "=f"(x), "=f"(y) : "l"(v));
}
// in-place packed ReLU: halves are independent regs; ptxas elides the pack/unpack
__device__ __forceinline__ ull relu2(ull v) {
    float a, b;
    unpk2(v, a, b);
    return pk2(fmaxf(a, 0.f), fmaxf(b, 0.f));
}
__device__ __forceinline__ float hadd2(ull v) {
    float a, b;
    unpk2(v, a, b);
    return a + b;
}
__device__ __forceinline__ float tanh_fast(float x) {
    float y;
    asm("tanh.approx.f32 %0, %1;" : "=f"(y) : "f"(x));
    return y;
}

// ---------------- shared-memory weight cache ----------------
// Flow hidden units PERMUTED: new n<16 -> orig 2n+1 (deg-2); n>=16 -> orig 2(n-16) (deg-1).
// enc3+proj folded: Wf[o][j] = sum_k W3[j][k]*proj[k][o]  (o=0..2, j=0..31), bias folded.
// All arrays sized to multiples of 16 floats -> every array 16B-aligned.
struct __align__(16) Smem {
    float W1[4 * 64];      // 256
    float B1[64];
    float W2[64 * 32];     // 2048
    float B2[32];
    float Wf[96];          // folded enc3*proj, column-major: Wf[o*32 + j]
    float Pbp[16];         // {beff0,0, beff1,0, beff2,0, 0...} as acc-init pairs
    float FhX0[10 * 32];   // x0 hidden weights, new unit order
    float FhX1[10 * 16];   // x1 hidden weights, block1 units only
    float Fbh[10 * 32];    // hidden bias, new order
    float FoMu2[10 * 32];  // wmu col2, new order (natural pairs)
    float FoAl2[10 * 32];  // wa  col2
    float FoMu1[10 * 16];  // wmu col1, block2 units only
    float FoAl1[10 * 16];  // wa  col1
    float FbA[10 * 8];     // per layer acc inits: {bmu1,0, ba1,0, bmu2,0, ba2,0}
    float Fb0[32];         // per layer: [2l]=bmu0, [2l+1]=exp(-tanh(ba0))
};

__global__ __launch_bounds__(128, 3)
void gsi_kernel(const float* __restrict__ states,
                const float* __restrict__ enc_w1, const float* __restrict__ enc_b1,
                const float* __restrict__ enc_w2, const float* __restrict__ enc_b2,
                const float* __restrict__ enc_w3, const float* __restrict__ enc_b3,
                const float* __restrict__ proj_w, const float* __restrict__ proj_b,
                const float* __restrict__ flow_wh, const float* __restrict__ flow_bh,
                const float* __restrict__ flow_wmu, const float* __restrict__ flow_bmu,
                const float* __restrict__ flow_wa, const float* __restrict__ flow_ba,
                float* __restrict__ out, int B) {
    __shared__ Smem sm;
    const int tid = threadIdx.x;

    // ---- cooperative weight load + bake ----
    for (int i = tid; i < 4 * 64; i += 128)  sm.W1[i] = enc_w1[i];
    for (int i = tid; i < 64;     i += 128)  sm.B1[i] = enc_b1[i];
    for (int i = tid; i < 64 * 32; i += 128) sm.W2[i] = enc_w2[i];
    for (int i = tid; i < 32;     i += 128)  sm.B2[i] = enc_b2[i];
    // folded enc3*proj: Wf[o*32+j] = sum_k W3[j][k]*proj[k][o]
    if (tid < 96) {
        int j = tid / 3, o = tid % 3;
        float s = 0.f;
#pragma unroll
        for (int k = 0; k < 8; k++) s += enc_w3[j * 8 + k] * proj_w[k * 3 + o];
        sm.Wf[o * 32 + j] = s;
    }
    // Pbp pairs owned exclusively by tid<8 (no overlapping writers)
    if (tid < 8) {
        float s = 0.f;
        if (tid < 3) {
            s = proj_b[tid];
#pragma unroll
            for (int k = 0; k < 8; k++) s += enc_b3[k] * proj_w[k * 3 + tid];
        }
        sm.Pbp[2 * tid]     = s;
        sm.Pbp[2 * tid + 1] = 0.f;
    }
    // flow bake with unit permutation
    for (int i = tid; i < 10 * 16; i += 128) {
        int l = i >> 4, n = i & 15;
        int uo = 2 * n + 1, ue = 2 * n;
        const float* wh = flow_wh + l * 96;
        sm.FhX0[l * 32 + n]      = wh[uo];
        sm.FhX0[l * 32 + 16 + n] = wh[ue];
        sm.FhX1[l * 16 + n]      = wh[32 + uo];
        sm.Fbh[l * 32 + n]       = flow_bh[l * 32 + uo];
        sm.Fbh[l * 32 + 16 + n]  = flow_bh[l * 32 + ue];
        sm.FoMu2[l * 32 + n]      = flow_wmu[l * 96 + uo * 3 + 2];
        sm.FoMu2[l * 32 + 16 + n] = flow_wmu[l * 96 + ue * 3 + 2];
        sm.FoAl2[l * 32 + n]      = flow_wa[l * 96 + uo * 3 + 2];
        sm.FoAl2[l * 32 + 16 + n] = flow_wa[l * 96 + ue * 3 + 2];
        sm.FoMu1[l * 16 + n] = flow_wmu[l * 96 + ue * 3 + 1];
        sm.FoAl1[l * 16 + n] = flow_wa[l * 96 + ue * 3 + 1];
    }
    if (tid < 10) {
        int l = tid;
        sm.FbA[l * 8 + 0] = flow_bmu[l * 3 + 1]; sm.FbA[l * 8 + 1] = 0.f;
        sm.FbA[l * 8 + 2] = flow_ba [l * 3 + 1]; sm.FbA[l * 8 + 3] = 0.f;
        sm.FbA[l * 8 + 4] = flow_bmu[l * 3 + 2]; sm.FbA[l * 8 + 5] = 0.f;
        sm.FbA[l * 8 + 6] = flow_ba [l * 3 + 2]; sm.FbA[l * 8 + 7] = 0.f;
        sm.Fb0[2 * l]     = flow_bmu[l * 3 + 0];
        sm.Fb0[2 * l + 1] = expf(-tanhf(flow_ba[l * 3 + 0]));
    }
    __syncthreads();

    const int rbase = blockIdx.x * (128 * R) + tid;

    ull xp[R][4];
#pragma unroll
    for (int q = 0; q < R; q++) {
        int rl = rbase + q * 128;
        if (rl > B - 1) rl = B - 1;                      // clamp load; store guarded later
        float4 sv = reinterpret_cast<const float4*>(states)[rl];
        xp[q][0] = pk2(sv.x, sv.x); xp[q][1] = pk2(sv.y, sv.y);
        xp[q][2] = pk2(sv.z, sv.z); xp[q][3] = pk2(sv.w, sv.w);
    }

    // ---- fused enc1 (4->64) + enc2 (64->32), single pass, h1 chunked by 8 ----
    ull h2[R][16];
    {
        const ulonglong2* pb = reinterpret_cast<const ulonglong2*>(sm.B2);
#pragma unroll
        for (int p = 0; p < 8; p++) {
            ulonglong2 v = pb[p];
#pragma unroll
            for (int q = 0; q < R; q++) { h2[q][2 * p] = v.x; h2[q][2 * p + 1] = v.y; }
        }
    }
#pragma unroll 1
    for (int c = 0; c < 8; c++) {
        ull h1[R][4];
        const ulonglong2* pb1 = reinterpret_cast<const ulonglong2*>(sm.B1 + c * 8);
#pragma unroll
        for (int p = 0; p < 2; p++) {
            ulonglong2 v = pb1[p];
#pragma unroll
            for (int q = 0; q < R; q++) { h1[q][2 * p] = v.x; h1[q][2 * p + 1] = v.y; }
        }
#pragma unroll
        for (int i = 0; i < 4; i++) {
            const ulonglong2* w = reinterpret_cast<const ulonglong2*>(sm.W1 + i * 64 + c * 8);
#pragma unroll
            for (int p = 0; p < 2; p++) {
                ulonglong2 v = w[p];
#pragma unroll
                for (int q = 0; q < R; q++) {
                    h1[q][2 * p]     = ffma2(xp[q][i], v.x, h1[q][2 * p]);
                    h1[q][2 * p + 1] = ffma2(xp[q][i], v.y, h1[q][2 * p + 1]);
                }
            }
        }
#pragma unroll
        for (int j = 0; j < 4; j++) {
            ull ab[R], bb[R];
#pragma unroll
            for (int q = 0; q < R; q++) {
                float a, b;
                unpk2(h1[q][j], a, b);
                a = fmaxf(a, 0.f); b = fmaxf(b, 0.f);
                ab[q] = pk2(a, a); bb[q] = pk2(b, b);
            }
            const int u = c * 8 + 2 * j;
            const ulonglong2* wa = reinterpret_cast<const ulonglong2*>(sm.W2 + u * 32);
            const ulonglong2* wb = reinterpret_cast<const ulonglong2*>(sm.W2 + u * 32 + 32);
#pragma unroll
            for (int p = 0; p < 8; p++) {
                ulonglong2 v = wa[p];
#pragma unroll
                for (int q = 0; q < R; q++) {
                    h2[q][2 * p]     = ffma2(ab[q], v.x, h2[q][2 * p]);
                    h2[q][2 * p + 1] = ffma2(ab[q], v.y, h2[q][2 * p + 1]);
                }
            }
#pragma unroll
            for (int p = 0; p < 8; p++) {
                ulonglong2 v = wb[p];
#pragma unroll
                for (int q = 0; q < R; q++) {
                    h2[q][2 * p]     = ffma2(bb[q], v.x, h2[q][2 * p]);
                    h2[q][2 * p + 1] = ffma2(bb[q], v.y, h2[q][2 * p + 1]);
                }
            }
        }
    }

    // ---- folded enc3+proj: 32 -> 3, dot-form (packed partial sums, no broadcasts) ----
    float x0[R], x1[R], x2[R];
    {
        ull ax0[R], ax1[R], ax2[R];
        {
            const ulonglong2* pb = reinterpret_cast<const ulonglong2*>(sm.Pbp);
            ulonglong2 v0 = pb[0];          // {beff0,0},{beff1,0}
            ull v2 = reinterpret_cast<const ull*>(sm.Pbp)[2];  // {beff2,0}
#pragma unroll
            for (int q = 0; q < R; q++) { ax0[q] = v0.x; ax1[q] = v0.y; ax2[q] = v2; }
        }
        const ull* w0p = reinterpret_cast<const ull*>(sm.Wf);
        const ull* w1p = reinterpret_cast<const ull*>(sm.Wf + 32);
        const ull* w2p = reinterpret_cast<const ull*>(sm.Wf + 64);
#pragma unroll
        for (int j = 0; j < 16; j++) {
            ull w0 = w0p[j], w1 = w1p[j], w2 = w2p[j];
#pragma unroll
            for (int q = 0; q < R; q++) {
                ull h = relu2(h2[q][j]);
                ax0[q] = ffma2(h, w0, ax0[q]);
                ax1[q] = ffma2(h, w1, ax1[q]);
                ax2[q] = ffma2(h, w2, ax2[q]);
            }
        }
#pragma unroll
        for (int q = 0; q < R; q++) {
            x0[q] = hadd2(ax0[q]); x1[q] = hadd2(ax1[q]); x2[q] = hadd2(ax2[q]);
        }
    }

    // ---- MAF flow: 10 layers; output stage dot-form (natural pairs, no broadcasts) ----
#pragma unroll 1
    for (int l = 0; l < 10; l++) {
        const float* fhx0 = sm.FhX0 + l * 32;
        const float* fhx1 = sm.FhX1 + l * 16;
        const float* fbh  = sm.Fbh  + l * 32;
        const ull* fmu2   = reinterpret_cast<const ull*>(sm.FoMu2 + l * 32);
        const ull* fal2   = reinterpret_cast<const ull*>(sm.FoAl2 + l * 32);
        const ull* fmu1   = reinterpret_cast<const ull*>(sm.FoMu1 + l * 16);
        const ull* fal1   = reinterpret_cast<const ull*>(sm.FoAl1 + l * 16);
        const float* fba  = sm.FbA + l * 8;
        const float* fb0  = sm.Fb0 + l * 2;

        ull x0b[R], x1b[R];
#pragma unroll
        for (int q = 0; q < R; q++) { x0b[q] = pk2(x0[q], x0[q]); x1b[q] = pk2(x1[q], x1[q]); }

        ull am1[R], aa1[R], am2[R], aa2[R];
        {
            const ulonglong2* pb = reinterpret_cast<const ulonglong2*>(fba);
            ulonglong2 v0 = pb[0], v1 = pb[1];  // {bmu1,0},{ba1,0},{bmu2,0},{ba2,0}
#pragma unroll
            for (int q = 0; q < R; q++) { am1[q] = v0.x; aa1[q] = v0.y; am2[q] = v1.x; aa2[q] = v1.y; }
        }

        // ---- block1: 16 deg-2 units (x0 + x1 inputs; feed mu2/al2 only) ----
        {
            ull hh[R][8];
            const ulonglong2* pbh = reinterpret_cast<const ulonglong2*>(fbh);
#pragma unroll
            for (int p = 0; p < 4; p++) {
                ulonglong2 v = pbh[p];
#pragma unroll
                for (int q = 0; q < R; q++) { hh[q][2 * p] = v.x; hh[q][2 * p + 1] = v.y; }
            }
            const ulonglong2* w0 = reinterpret_cast<const ulonglong2*>(fhx0);
            const ulonglong2* w1 = reinterpret_cast<const ulonglong2*>(fhx1);
#pragma unroll
            for (int p = 0; p < 4; p++) {
                ulonglong2 v = w0[p];
#pragma unroll
                for (int q = 0; q < R; q++) {
                    hh[q][2 * p]     = ffma2(x0b[q], v.x, hh[q][2 * p]);
                    hh[q][2 * p + 1] = ffma2(x0b[q], v.y, hh[q][2 * p + 1]);
                }
            }
#pragma unroll
            for (int p = 0; p < 4; p++) {
                ulonglong2 v = w1[p];
#pragma unroll
                for (int q = 0; q < R; q++) {
                    hh[q][2 * p]     = ffma2(x1b[q], v.x, hh[q][2 * p]);
                    hh[q][2 * p + 1] = ffma2(x1b[q], v.y, hh[q][2 * p + 1]);
                }
            }
#pragma unroll
            for (int p = 0; p < 8; p++) {
                ull wm2 = fmu2[p], wa2 = fal2[p];
#pragma unroll
                for (int q = 0; q < R; q++) {
                    ull h = relu2(hh[q][p]);
                    am2[q] = ffma2(h, wm2, am2[q]);
                    aa2[q] = ffma2(h, wa2, aa2[q]);
                }
            }
        }
        // ---- block2: 16 deg-1 units (x0 only; feed mu1/al1 AND mu2/al2) ----
        {
            ull hh[R][8];
            const ulonglong2* pbh = reinterpret_cast<const ulonglong2*>(fbh + 16);
#pragma unroll
            for (int p = 0; p < 4; p++) {
                ulonglong2 v = pbh[p];
#pragma unroll
                for (int q = 0; q < R; q++) { hh[q][2 * p] = v.x; hh[q][2 * p + 1] = v.y; }
            }
            const ulonglong2* w0 = reinterpret_cast<const ulonglong2*>(fhx0 + 16);
#pragma unroll
            for (int p = 0; p < 4; p++) {
                ulonglong2 v = w0[p];
#pragma unroll
                for (int q = 0; q < R; q++) {
                    hh[q][2 * p]     = ffma2(x0b[q], v.x, hh[q][2 * p]);
                    hh[q][2 * p + 1] = ffma2(x0b[q], v.y, hh[q][2 * p + 1]);
                }
            }
#pragma unroll
            for (int p = 0; p < 8; p++) {
                ull wm2 = fmu2[8 + p], wa2 = fal2[8 + p];
                ull wm1 = fmu1[p],     wa1 = fal1[p];
#pragma unroll
                for (int q = 0; q < R; q++) {
                    ull h = relu2(hh[q][p]);
                    am2[q] = ffma2(h, wm2, am2[q]);
                    aa2[q] = ffma2(h, wa2, aa2[q]);
                    am1[q] = ffma2(h, wm1, am1[q]);
                    aa1[q] = ffma2(h, wa1, aa1[q]);
                }
            }
        }

        float bmu0 = fb0[0], esc0 = fb0[1];
#pragma unroll
        for (int q = 0; q < R; q++) {
            float mu1 = hadd2(am1[q]), al1 = hadd2(aa1[q]);
            float mu2 = hadd2(am2[q]), al2 = hadd2(aa2[q]);
            float t1 = tanh_fast(al1);
            float t2 = tanh_fast(al2);
            float nx0 = (x0[q] - bmu0) * esc0;
            float nx1 = (x1[q] - mu1) * __expf(-t1);
            float nx2 = (x2[q] - mu2) * __expf(-t2);
            x0[q] = nx2; x1[q] = nx1; x2[q] = nx0;
        }
    }

    // ---- squash + HSV + store  (sigmoid(x) = 0.5*(1+tanh(x/2))) ----
#pragma unroll
    for (int q = 0; q < R; q++) {
        int rq = rbase + q * 128;
        if (rq < B) {
            float t0 = tanh_fast(0.5f * x0[q]);
            float t1 = tanh_fast(0.5f * x1[q]);
            float t2 = tanh_fast(0.5f * x2[q]);
            out[3 * rq + 0] = fmaf(3.14159265358979323846f, t0, 3.14159265358979323846f);
            out[3 * rq + 1] = fmaf(0.5f, t1, 0.5f);
            out[3 * rq + 2] = fmaf(0.5f, t2, 0.5f);
        }
    }
}

extern "C" void kernel_launch(void* const* d_in, const int* in_sizes, int n_in,
                              void* d_out, int out_size) {
    (void)n_in; (void)out_size;
    const float* states   = (const float*)d_in[0];
    const float* enc_w1   = (const float*)d_in[1];
    const float* enc_b1   = (const float*)d_in[2];
    const float* enc_w2   = (const float*)d_in[3];
    const float* enc_b2   = (const float*)d_in[4];
    const float* enc_w3   = (const float*)d_in[5];
    const float* enc_b3   = (const float*)d_in[6];
    const float* proj_w   = (const float*)d_in[7];
    const float* proj_b   = (const float*)d_in[8];
    const float* flow_wh  = (const float*)d_in[9];
    const float* flow_bh  = (const float*)d_in[10];
    const float* flow_wmu = (const float*)d_in[11];
    const float* flow_bmu = (const float*)d_in[12];
    const float* flow_wa  = (const float*)d_in[13];
    const float* flow_ba  = (const float*)d_in[14];

    const int B = in_sizes[0] / 4;
    const int grid = (B + 128 * R - 1) / (128 * R);
    gsi_kernel<<<grid, 128>>>(states, enc_w1, enc_b1, enc_w2, enc_b2, enc_w3, enc_b3,
                              proj_w, proj_b, flow_wh, flow_bh, flow_wmu, flow_bmu,
                              flow_wa, flow_ba, (float*)d_out, B);
}

// round 10
// speedup vs baseline: 1.2301x; 1.0968x over previous
#include <cuda_runtime.h>

using ull = unsigned long long;

#define R 3

// ---------------- f32x2 packed-math helpers (Blackwell FFMA2 path) ----------------

__device__ __forceinline__ ull ffma2(ull a, ull b, ull c) {
    ull d;
    asm("fma.rn.f32x2 %0, %1, %2, %3;" : "=l"(d) : "l"(a), "l"(b), "l"(c));
    return d;
}
__device__ __forceinline__ ull pk2(float x, float y) {
    ull r;
    asm("mov.b64 %0, {%1, %2};" : "=l"(r) : "f"(x), "f"(y));
    return r;
}
__device__ __forceinline__ void unpk2(ull v, float& x, float& y) {
    asm("mov.b64 {%0, %1}, %2;" : "=f"(x), "=f"(y) : "l"(v));
}
__device__ __forceinline__ ull relu2(ull v) {
    float a, b;
    unpk2(v, a, b);
    return pk2(fmaxf(a, 0.f), fmaxf(b, 0.f));
}
__device__ __forceinline__ float hadd2(ull v) {
    float a, b;
    unpk2(v, a, b);
    return a + b;
}
__device__ __forceinline__ float tanh_fast(float x) {
    float y;
    asm("tanh.approx.f32 %0, %1;" : "=f"(y) : "f"(x));
    return y;
}

// ---------------- constant-memory weight cache (warp-uniform -> LDCU/UR path) ----------------
// Same baked layout as R9's Smem; all array lengths multiples of 4 floats (16B).
struct __align__(16) CParams {
    float W1[4 * 64];      // 256
    float B1[64];
    float W2[64 * 32];     // 2048
    float B2[32];
    float Wf[96];          // folded enc3*proj, column-major: Wf[o*32 + j]
    float Pbp[16];         // {beff0,0, beff1,0, beff2,0, 0...}
    float FhX0[10 * 32];
    float FhX1[10 * 16];
    float Fbh[10 * 32];
    float FoMu2[10 * 32];
    float FoAl2[10 * 32];
    float FoMu1[10 * 16];
    float FoAl1[10 * 16];
    float FbA[10 * 8];     // {bmu1,0, ba1,0, bmu2,0, ba2,0}
    float Fb0[32];         // [2l]=bmu0, [2l+1]=exp(-tanh(ba0))
};

__constant__ CParams cP;
__device__ CParams g_stage;

// ---------------- bake kernel: fold/permute weights into g_stage (1 block, 128 thr) ----------------
__global__ void bake_kernel(const float* __restrict__ enc_w1, const float* __restrict__ enc_b1,
                            const float* __restrict__ enc_w2, const float* __restrict__ enc_b2,
                            const float* __restrict__ enc_w3, const float* __restrict__ enc_b3,
                            const float* __restrict__ proj_w, const float* __restrict__ proj_b,
                            const float* __restrict__ flow_wh, const float* __restrict__ flow_bh,
                            const float* __restrict__ flow_wmu, const float* __restrict__ flow_bmu,
                            const float* __restrict__ flow_wa, const float* __restrict__ flow_ba) {
    const int tid = threadIdx.x;
    for (int i = tid; i < 4 * 64; i += 128)  g_stage.W1[i] = enc_w1[i];
    for (int i = tid; i < 64;     i += 128)  g_stage.B1[i] = enc_b1[i];
    for (int i = tid; i < 64 * 32; i += 128) g_stage.W2[i] = enc_w2[i];
    for (int i = tid; i < 32;     i += 128)  g_stage.B2[i] = enc_b2[i];
    if (tid < 96) {
        int j = tid / 3, o = tid % 3;
        float s = 0.f;
#pragma unroll
        for (int k = 0; k < 8; k++) s += enc_w3[j * 8 + k] * proj_w[k * 3 + o];
        g_stage.Wf[o * 32 + j] = s;
    }
    if (tid < 8) {
        float s = 0.f;
        if (tid < 3) {
            s = proj_b[tid];
#pragma unroll
            for (int k = 0; k < 8; k++) s += enc_b3[k] * proj_w[k * 3 + tid];
        }
        g_stage.Pbp[2 * tid]     = s;
        g_stage.Pbp[2 * tid + 1] = 0.f;
    }
    // flow bake with unit permutation (n<16: u=2n+1 deg-2; n>=16: u=2(n-16) deg-1)
    for (int i = tid; i < 10 * 16; i += 128) {
        int l = i >> 4, n = i & 15;
        int uo = 2 * n + 1, ue = 2 * n;
        const float* wh = flow_wh + l * 96;
        g_stage.FhX0[l * 32 + n]      = wh[uo];
        g_stage.FhX0[l * 32 + 16 + n] = wh[ue];
        g_stage.FhX1[l * 16 + n]      = wh[32 + uo];
        g_stage.Fbh[l * 32 + n]       = flow_bh[l * 32 + uo];
        g_stage.Fbh[l * 32 + 16 + n]  = flow_bh[l * 32 + ue];
        g_stage.FoMu2[l * 32 + n]      = flow_wmu[l * 96 + uo * 3 + 2];
        g_stage.FoMu2[l * 32 + 16 + n] = flow_wmu[l * 96 + ue * 3 + 2];
        g_stage.FoAl2[l * 32 + n]      = flow_wa[l * 96 + uo * 3 + 2];
        g_stage.FoAl2[l * 32 + 16 + n] = flow_wa[l * 96 + ue * 3 + 2];
        g_stage.FoMu1[l * 16 + n] = flow_wmu[l * 96 + ue * 3 + 1];
        g_stage.FoAl1[l * 16 + n] = flow_wa[l * 96 + ue * 3 + 1];
    }
    if (tid < 10) {
        int l = tid;
        g_stage.FbA[l * 8 + 0] = flow_bmu[l * 3 + 1]; g_stage.FbA[l * 8 + 1] = 0.f;
        g_stage.FbA[l * 8 + 2] = flow_ba [l * 3 + 1]; g_stage.FbA[l * 8 + 3] = 0.f;
        g_stage.FbA[l * 8 + 4] = flow_bmu[l * 3 + 2]; g_stage.FbA[l * 8 + 5] = 0.f;
        g_stage.FbA[l * 8 + 6] = flow_ba [l * 3 + 2]; g_stage.FbA[l * 8 + 7] = 0.f;
        g_stage.Fb0[2 * l]     = flow_bmu[l * 3 + 0];
        g_stage.Fb0[2 * l + 1] = expf(-tanhf(flow_ba[l * 3 + 0]));
    }
}

// ---------------- main kernel: R9 body with const-space weights ----------------

__global__ __launch_bounds__(128, 3)
void gsi_kernel(const float* __restrict__ states, float* __restrict__ out, int B) {
    const int tid = threadIdx.x;
    const int rbase = blockIdx.x * (128 * R) + tid;

    ull xp[R][4];
#pragma unroll
    for (int q = 0; q < R; q++) {
        int rl = rbase + q * 128;
        if (rl > B - 1) rl = B - 1;                      // clamp load; store guarded later
        float4 sv = reinterpret_cast<const float4*>(states)[rl];
        xp[q][0] = pk2(sv.x, sv.x); xp[q][1] = pk2(sv.y, sv.y);
        xp[q][2] = pk2(sv.z, sv.z); xp[q][3] = pk2(sv.w, sv.w);
    }

    // ---- fused enc1 (4->64) + enc2 (64->32), single pass, h1 chunked by 8 ----
    ull h2[R][16];
    {
        const ulonglong2* pb = reinterpret_cast<const ulonglong2*>(cP.B2);
#pragma unroll
        for (int p = 0; p < 8; p++) {
            ulonglong2 v = pb[p];
#pragma unroll
            for (int q = 0; q < R; q++) { h2[q][2 * p] = v.x; h2[q][2 * p + 1] = v.y; }
        }
    }
#pragma unroll 1
    for (int c = 0; c < 8; c++) {
        ull h1[R][4];
        const ulonglong2* pb1 = reinterpret_cast<const ulonglong2*>(cP.B1 + c * 8);
#pragma unroll
        for (int p = 0; p < 2; p++) {
            ulonglong2 v = pb1[p];
#pragma unroll
            for (int q = 0; q < R; q++) { h1[q][2 * p] = v.x; h1[q][2 * p + 1] = v.y; }
        }
#pragma unroll
        for (int i = 0; i < 4; i++) {
            const ulonglong2* w = reinterpret_cast<const ulonglong2*>(cP.W1 + i * 64 + c * 8);
#pragma unroll
            for (int p = 0; p < 2; p++) {
                ulonglong2 v = w[p];
#pragma unroll
                for (int q = 0; q < R; q++) {
                    h1[q][2 * p]     = ffma2(xp[q][i], v.x, h1[q][2 * p]);
                    h1[q][2 * p + 1] = ffma2(xp[q][i], v.y, h1[q][2 * p + 1]);
                }
            }
        }
#pragma unroll
        for (int j = 0; j < 4; j++) {
            ull ab[R], bb[R];
#pragma unroll
            for (int q = 0; q < R; q++) {
                float a, b;
                unpk2(h1[q][j], a, b);
                a = fmaxf(a, 0.f); b = fmaxf(b, 0.f);
                ab[q] = pk2(a, a); bb[q] = pk2(b, b);
            }
            const int u = c * 8 + 2 * j;
            const ulonglong2* wa = reinterpret_cast<const ulonglong2*>(cP.W2 + u * 32);
            const ulonglong2* wb = reinterpret_cast<const ulonglong2*>(cP.W2 + u * 32 + 32);
#pragma unroll
            for (int p = 0; p < 8; p++) {
                ulonglong2 v = wa[p];
#pragma unroll
                for (int q = 0; q < R; q++) {
                    h2[q][2 * p]     = ffma2(ab[q], v.x, h2[q][2 * p]);
                    h2[q][2 * p + 1] = ffma2(ab[q], v.y, h2[q][2 * p + 1]);
                }
            }
#pragma unroll
            for (int p = 0; p < 8; p++) {
                ulonglong2 v = wb[p];
#pragma unroll
                for (int q = 0; q < R; q++) {
                    h2[q][2 * p]     = ffma2(bb[q], v.x, h2[q][2 * p]);
                    h2[q][2 * p + 1] = ffma2(bb[q], v.y, h2[q][2 * p + 1]);
                }
            }
        }
    }

    // ---- folded enc3+proj: 32 -> 3, dot-form ----
    float x0[R], x1[R], x2[R];
    {
        ull ax0[R], ax1[R], ax2[R];
        {
            const ulonglong2* pb = reinterpret_cast<const ulonglong2*>(cP.Pbp);
            ulonglong2 v0 = pb[0];
            ull v2 = reinterpret_cast<const ull*>(cP.Pbp)[2];
#pragma unroll
            for (int q = 0; q < R; q++) { ax0[q] = v0.x; ax1[q] = v0.y; ax2[q] = v2; }
        }
        const ull* w0p = reinterpret_cast<const ull*>(cP.Wf);
        const ull* w1p = reinterpret_cast<const ull*>(cP.Wf + 32);
        const ull* w2p = reinterpret_cast<const ull*>(cP.Wf + 64);
#pragma unroll
        for (int j = 0; j < 16; j++) {
            ull w0 = w0p[j], w1 = w1p[j], w2 = w2p[j];
#pragma unroll
            for (int q = 0; q < R; q++) {
                ull h = relu2(h2[q][j]);
                ax0[q] = ffma2(h, w0, ax0[q]);
                ax1[q] = ffma2(h, w1, ax1[q]);
                ax2[q] = ffma2(h, w2, ax2[q]);
            }
        }
#pragma unroll
        for (int q = 0; q < R; q++) {
            x0[q] = hadd2(ax0[q]); x1[q] = hadd2(ax1[q]); x2[q] = hadd2(ax2[q]);
        }
    }

    // ---- MAF flow: 10 layers; output stage dot-form ----
#pragma unroll 1
    for (int l = 0; l < 10; l++) {
        const float* fhx0 = cP.FhX0 + l * 32;
        const float* fhx1 = cP.FhX1 + l * 16;
        const float* fbh  = cP.Fbh  + l * 32;
        const ull* fmu2   = reinterpret_cast<const ull*>(cP.FoMu2 + l * 32);
        const ull* fal2   = reinterpret_cast<const ull*>(cP.FoAl2 + l * 32);
        const ull* fmu1   = reinterpret_cast<const ull*>(cP.FoMu1 + l * 16);
        const ull* fal1   = reinterpret_cast<const ull*>(cP.FoAl1 + l * 16);
        const float* fba  = cP.FbA + l * 8;
        const float* fb0  = cP.Fb0 + l * 2;

        ull x0b[R], x1b[R];
#pragma unroll
        for (int q = 0; q < R; q++) { x0b[q] = pk2(x0[q], x0[q]); x1b[q] = pk2(x1[q], x1[q]); }

        ull am1[R], aa1[R], am2[R], aa2[R];
        {
            const ulonglong2* pb = reinterpret_cast<const ulonglong2*>(fba);
            ulonglong2 v0 = pb[0], v1 = pb[1];
#pragma unroll
            for (int q = 0; q < R; q++) { am1[q] = v0.x; aa1[q] = v0.y; am2[q] = v1.x; aa2[q] = v1.y; }
        }

        // ---- block1: 16 deg-2 units (x0 + x1 inputs; feed mu2/al2 only) ----
        {
            ull hh[R][8];
            const ulonglong2* pbh = reinterpret_cast<const ulonglong2*>(fbh);
#pragma unroll
            for (int p = 0; p < 4; p++) {
                ulonglong2 v = pbh[p];
#pragma unroll
                for (int q = 0; q < R; q++) { hh[q][2 * p] = v.x; hh[q][2 * p + 1] = v.y; }
            }
            const ulonglong2* w0 = reinterpret_cast<const ulonglong2*>(fhx0);
            const ulonglong2* w1 = reinterpret_cast<const ulonglong2*>(fhx1);
#pragma unroll
            for (int p = 0; p < 4; p++) {
                ulonglong2 v = w0[p];
#pragma unroll
                for (int q = 0; q < R; q++) {
                    hh[q][2 * p]     = ffma2(x0b[q], v.x, hh[q][2 * p]);
                    hh[q][2 * p + 1] = ffma2(x0b[q], v.y, hh[q][2 * p + 1]);
                }
            }
#pragma unroll
            for (int p = 0; p < 4; p++) {
                ulonglong2 v = w1[p];
#pragma unroll
                for (int q = 0; q < R; q++) {
                    hh[q][2 * p]     = ffma2(x1b[q], v.x, hh[q][2 * p]);
                    hh[q][2 * p + 1] = ffma2(x1b[q], v.y, hh[q][2 * p + 1]);
                }
            }
#pragma unroll
            for (int p = 0; p < 8; p++) {
                ull wm2 = fmu2[p], wa2 = fal2[p];
#pragma unroll
                for (int q = 0; q < R; q++) {
                    ull h = relu2(hh[q][p]);
                    am2[q] = ffma2(h, wm2, am2[q]);
                    aa2[q] = ffma2(h, wa2, aa2[q]);
                }
            }
        }
        // ---- block2: 16 deg-1 units (x0 only; feed mu1/al1 AND mu2/al2) ----
        {
            ull hh[R][8];
            const ulonglong2* pbh = reinterpret_cast<const ulonglong2*>(fbh + 16);
#pragma unroll
            for (int p = 0; p < 4; p++) {
                ulonglong2 v = pbh[p];
#pragma unroll
                for (int q = 0; q < R; q++) { hh[q][2 * p] = v.x; hh[q][2 * p + 1] = v.y; }
            }
            const ulonglong2* w0 = reinterpret_cast<const ulonglong2*>(fhx0 + 16);
#pragma unroll
            for (int p = 0; p < 4; p++) {
                ulonglong2 v = w0[p];
#pragma unroll
                for (int q = 0; q < R; q++) {
                    hh[q][2 * p]     = ffma2(x0b[q], v.x, hh[q][2 * p]);
                    hh[q][2 * p + 1] = ffma2(x0b[q], v.y, hh[q][2 * p + 1]);
                }
            }
#pragma unroll
            for (int p = 0; p < 8; p++) {
                ull wm2 = fmu2[8 + p], wa2 = fal2[8 + p];
                ull wm1 = fmu1[p],     wa1 = fal1[p];
#pragma unroll
                for (int q = 0; q < R; q++) {
                    ull h = relu2(hh[q][p]);
                    am2[q] = ffma2(h, wm2, am2[q]);
                    aa2[q] = ffma2(h, wa2, aa2[q]);
                    am1[q] = ffma2(h, wm1, am1[q]);
                    aa1[q] = ffma2(h, wa1, aa1[q]);
                }
            }
        }

        float bmu0 = fb0[0], esc0 = fb0[1];
#pragma unroll
        for (int q = 0; q < R; q++) {
            float mu1 = hadd2(am1[q]), al1 = hadd2(aa1[q]);
            float mu2 = hadd2(am2[q]), al2 = hadd2(aa2[q]);
            float t1 = tanh_fast(al1);
            float t2 = tanh_fast(al2);
            float nx0 = (x0[q] - bmu0) * esc0;
            float nx1 = (x1[q] - mu1) * __expf(-t1);
            float nx2 = (x2[q] - mu2) * __expf(-t2);
            x0[q] = nx2; x1[q] = nx1; x2[q] = nx0;
        }
    }

    // ---- squash + HSV + store  (sigmoid(x) = 0.5*(1+tanh(x/2))) ----
#pragma unroll
    for (int q = 0; q < R; q++) {
        int rq = rbase + q * 128;
        if (rq < B) {
            float t0 = tanh_fast(0.5f * x0[q]);
            float t1 = tanh_fast(0.5f * x1[q]);
            float t2 = tanh_fast(0.5f * x2[q]);
            out[3 * rq + 0] = fmaf(3.14159265358979323846f, t0, 3.14159265358979323846f);
            out[3 * rq + 1] = fmaf(0.5f, t1, 0.5f);
            out[3 * rq + 2] = fmaf(0.5f, t2, 0.5f);
        }
    }
}

extern "C" void kernel_launch(void* const* d_in, const int* in_sizes, int n_in,
                              void* d_out, int out_size) {
    (void)n_in; (void)out_size;
    const float* states   = (const float*)d_in[0];
    const float* enc_w1   = (const float*)d_in[1];
    const float* enc_b1   = (const float*)d_in[2];
    const float* enc_w2   = (const float*)d_in[3];
    const float* enc_b2   = (const float*)d_in[4];
    const float* enc_w3   = (const float*)d_in[5];
    const float* enc_b3   = (const float*)d_in[6];
    const float* proj_w   = (const float*)d_in[7];
    const float* proj_b   = (const float*)d_in[8];
    const float* flow_wh  = (const float*)d_in[9];
    const float* flow_bh  = (const float*)d_in[10];
    const float* flow_wmu = (const float*)d_in[11];
    const float* flow_bmu = (const float*)d_in[12];
    const float* flow_wa  = (const float*)d_in[13];
    const float* flow_ba  = (const float*)d_in[14];

    // 1) bake folded/permuted weights into device staging
    bake_kernel<<<1, 128>>>(enc_w1, enc_b1, enc_w2, enc_b2, enc_w3, enc_b3,
                            proj_w, proj_b, flow_wh, flow_bh, flow_wmu, flow_bmu,
                            flow_wa, flow_ba);
    // 2) staging -> __constant__ (D2D async; graph-capturable, no allocation)
    void* stage_ptr = nullptr;
    cudaGetSymbolAddress(&stage_ptr, g_stage);
    cudaMemcpyToSymbolAsync(cP, stage_ptr, sizeof(CParams), 0,
                            cudaMemcpyDeviceToDevice, 0);
    // 3) main kernel reads weights through the const/LDCU uniform path
    const int B = in_sizes[0] / 4;
    const int grid = (B + 128 * R - 1) / (128 * R);
    gsi_kernel<<<grid, 128>>>(states, (float*)d_out, B);
}

// round 11
// speedup vs baseline: 1.2829x; 1.0429x over previous
#include <cuda_runtime.h>

using ull = unsigned long long;

#define R 3

// ---------------- f32x2 packed-math helpers (Blackwell FFMA2 path) ----------------

__device__ __forceinline__ ull ffma2(ull a, ull b, ull c) {
    ull d;
    asm("fma.rn.f32x2 %0, %1, %2, %3;" : "=l"(d) : "l"(a), "l"(b), "l"(c));
    return d;
}
__device__ __forceinline__ ull pk2(float x, float y) {
    ull r;
    asm("mov.b64 %0, {%1, %2};" : "=l"(r) : "f"(x), "f"(y));
    return r;
}
__device__ __forceinline__ void unpk2(ull v, float& x, float& y) {
    asm("mov.b64 {%0, %1}, %2;" : "=f"(x), "=f"(y) : "l"(v));
}
__device__ __forceinline__ ull relu2(ull v) {
    float a, b;
    unpk2(v, a, b);
    return pk2(fmaxf(a, 0.f), fmaxf(b, 0.f));
}
__device__ __forceinline__ float hadd2(ull v) {
    float a, b;
    unpk2(v, a, b);
    return a + b;
}
__device__ __forceinline__ float tanh_fast(float x) {
    float y;
    asm("tanh.approx.f32 %0, %1;" : "=f"(y) : "f"(x));
    return y;
}

// ---------------- constant-memory weight cache (warp-uniform -> LDCU/UR path) ----------------
struct __align__(16) CParams {
    float W1[4 * 64];      // 256
    float B1[64];
    float W2[64 * 32];     // 2048
    float B2[32];
    float Wf[96];          // folded enc3*proj, column-major: Wf[o*32 + j]
    float Pbp[16];         // {beff0,0, beff1,0, beff2,0, 0...}
    float FhX0[10 * 32];
    float FhX1[10 * 16];
    float Fbh[10 * 32];
    float FoMu2[10 * 32];
    float FoAl2[10 * 32];
    float FoMu1[10 * 16];
    float FoAl1[10 * 16];
    float FbA[10 * 8];     // {bmu1,0, ba1,0, bmu2,0, ba2,0}
    float Fb0[32];         // [2l]=bmu0, [2l+1]=exp(-tanh(ba0))
};

__constant__ CParams cP;
__device__ CParams g_stage;

// ---------------- bake kernel: fold/permute weights into g_stage (1 block, 128 thr) ----------------
__global__ void bake_kernel(const float* __restrict__ enc_w1, const float* __restrict__ enc_b1,
                            const float* __restrict__ enc_w2, const float* __restrict__ enc_b2,
                            const float* __restrict__ enc_w3, const float* __restrict__ enc_b3,
                            const float* __restrict__ proj_w, const float* __restrict__ proj_b,
                            const float* __restrict__ flow_wh, const float* __restrict__ flow_bh,
                            const float* __restrict__ flow_wmu, const float* __restrict__ flow_bmu,
                            const float* __restrict__ flow_wa, const float* __restrict__ flow_ba) {
    const int tid = threadIdx.x;
    for (int i = tid; i < 4 * 64; i += 128)  g_stage.W1[i] = enc_w1[i];
    for (int i = tid; i < 64;     i += 128)  g_stage.B1[i] = enc_b1[i];
    for (int i = tid; i < 64 * 32; i += 128) g_stage.W2[i] = enc_w2[i];
    for (int i = tid; i < 32;     i += 128)  g_stage.B2[i] = enc_b2[i];
    if (tid < 96) {
        int j = tid / 3, o = tid % 3;
        float s = 0.f;
#pragma unroll
        for (int k = 0; k < 8; k++) s += enc_w3[j * 8 + k] * proj_w[k * 3 + o];
        g_stage.Wf[o * 32 + j] = s;
    }
    if (tid < 8) {
        float s = 0.f;
        if (tid < 3) {
            s = proj_b[tid];
#pragma unroll
            for (int k = 0; k < 8; k++) s += enc_b3[k] * proj_w[k * 3 + tid];
        }
        g_stage.Pbp[2 * tid]     = s;
        g_stage.Pbp[2 * tid + 1] = 0.f;
    }
    // flow bake with unit permutation (n<16: u=2n+1 deg-2; n>=16: u=2(n-16) deg-1)
    for (int i = tid; i < 10 * 16; i += 128) {
        int l = i >> 4, n = i & 15;
        int uo = 2 * n + 1, ue = 2 * n;
        const float* wh = flow_wh + l * 96;
        g_stage.FhX0[l * 32 + n]      = wh[uo];
        g_stage.FhX0[l * 32 + 16 + n] = wh[ue];
        g_stage.FhX1[l * 16 + n]      = wh[32 + uo];
        g_stage.Fbh[l * 32 + n]       = flow_bh[l * 32 + uo];
        g_stage.Fbh[l * 32 + 16 + n]  = flow_bh[l * 32 + ue];
        g_stage.FoMu2[l * 32 + n]      = flow_wmu[l * 96 + uo * 3 + 2];
        g_stage.FoMu2[l * 32 + 16 + n] = flow_wmu[l * 96 + ue * 3 + 2];
        g_stage.FoAl2[l * 32 + n]      = flow_wa[l * 96 + uo * 3 + 2];
        g_stage.FoAl2[l * 32 + 16 + n] = flow_wa[l * 96 + ue * 3 + 2];
        g_stage.FoMu1[l * 16 + n] = flow_wmu[l * 96 + ue * 3 + 1];
        g_stage.FoAl1[l * 16 + n] = flow_wa[l * 96 + ue * 3 + 1];
    }
    if (tid < 10) {
        int l = tid;
        g_stage.FbA[l * 8 + 0] = flow_bmu[l * 3 + 1]; g_stage.FbA[l * 8 + 1] = 0.f;
        g_stage.FbA[l * 8 + 2] = flow_ba [l * 3 + 1]; g_stage.FbA[l * 8 + 3] = 0.f;
        g_stage.FbA[l * 8 + 4] = flow_bmu[l * 3 + 2]; g_stage.FbA[l * 8 + 5] = 0.f;
        g_stage.FbA[l * 8 + 6] = flow_ba [l * 3 + 2]; g_stage.FbA[l * 8 + 7] = 0.f;
        g_stage.Fb0[2 * l]     = flow_bmu[l * 3 + 0];
        g_stage.Fb0[2 * l + 1] = expf(-tanhf(flow_ba[l * 3 + 0]));
    }
}

// ---------------- main kernel: const-space weights, 4 blocks/SM ----------------

__global__ __launch_bounds__(128, 4)
void gsi_kernel(const float* __restrict__ states, float* __restrict__ out, int B) {
    const int tid = threadIdx.x;
    const int rbase = blockIdx.x * (128 * R) + tid;

    ull xp[R][4];
#pragma unroll
    for (int q = 0; q < R; q++) {
        int rl = rbase + q * 128;
        if (rl > B - 1) rl = B - 1;                      // clamp load; store guarded later
        float4 sv = reinterpret_cast<const float4*>(states)[rl];
        xp[q][0] = pk2(sv.x, sv.x); xp[q][1] = pk2(sv.y, sv.y);
        xp[q][2] = pk2(sv.z, sv.z); xp[q][3] = pk2(sv.w, sv.w);
    }

    // ---- fused enc1 (4->64) + enc2 (64->32), single pass, h1 chunked by 8 ----
    ull h2[R][16];
    {
        const ulonglong2* pb = reinterpret_cast<const ulonglong2*>(cP.B2);
#pragma unroll
        for (int p = 0; p < 8; p++) {
            ulonglong2 v = pb[p];
#pragma unroll
            for (int q = 0; q < R; q++) { h2[q][2 * p] = v.x; h2[q][2 * p + 1] = v.y; }
        }
    }
#pragma unroll 1
    for (int c = 0; c < 8; c++) {
        ull h1[R][4];
        const ulonglong2* pb1 = reinterpret_cast<const ulonglong2*>(cP.B1 + c * 8);
#pragma unroll
        for (int p = 0; p < 2; p++) {
            ulonglong2 v = pb1[p];
#pragma unroll
            for (int q = 0; q < R; q++) { h1[q][2 * p] = v.x; h1[q][2 * p + 1] = v.y; }
        }
#pragma unroll
        for (int i = 0; i < 4; i++) {
            const ulonglong2* w = reinterpret_cast<const ulonglong2*>(cP.W1 + i * 64 + c * 8);
#pragma unroll
            for (int p = 0; p < 2; p++) {
                ulonglong2 v = w[p];
#pragma unroll
                for (int q = 0; q < R; q++) {
                    h1[q][2 * p]     = ffma2(xp[q][i], v.x, h1[q][2 * p]);
                    h1[q][2 * p + 1] = ffma2(xp[q][i], v.y, h1[q][2 * p + 1]);
                }
            }
        }
#pragma unroll
        for (int j = 0; j < 4; j++) {
            ull ab[R], bb[R];
#pragma unroll
            for (int q = 0; q < R; q++) {
                float a, b;
                unpk2(h1[q][j], a, b);
                a = fmaxf(a, 0.f); b = fmaxf(b, 0.f);
                ab[q] = pk2(a, a); bb[q] = pk2(b, b);
            }
            const int u = c * 8 + 2 * j;
            const ulonglong2* wa = reinterpret_cast<const ulonglong2*>(cP.W2 + u * 32);
            const ulonglong2* wb = reinterpret_cast<const ulonglong2*>(cP.W2 + u * 32 + 32);
#pragma unroll
            for (int p = 0; p < 8; p++) {
                ulonglong2 v = wa[p];
#pragma unroll
                for (int q = 0; q < R; q++) {
                    h2[q][2 * p]     = ffma2(ab[q], v.x, h2[q][2 * p]);
                    h2[q][2 * p + 1] = ffma2(ab[q], v.y, h2[q][2 * p + 1]);
                }
            }
#pragma unroll
            for (int p = 0; p < 8; p++) {
                ulonglong2 v = wb[p];
#pragma unroll
                for (int q = 0; q < R; q++) {
                    h2[q][2 * p]     = ffma2(bb[q], v.x, h2[q][2 * p]);
                    h2[q][2 * p + 1] = ffma2(bb[q], v.y, h2[q][2 * p + 1]);
                }
            }
        }
    }

    // ---- folded enc3+proj: 32 -> 3, dot-form ----
    float x0[R], x1[R], x2[R];
    {
        ull ax0[R], ax1[R], ax2[R];
        {
            const ulonglong2* pb = reinterpret_cast<const ulonglong2*>(cP.Pbp);
            ulonglong2 v0 = pb[0];
            ull v2 = reinterpret_cast<const ull*>(cP.Pbp)[2];
#pragma unroll
            for (int q = 0; q < R; q++) { ax0[q] = v0.x; ax1[q] = v0.y; ax2[q] = v2; }
        }
        const ull* w0p = reinterpret_cast<const ull*>(cP.Wf);
        const ull* w1p = reinterpret_cast<const ull*>(cP.Wf + 32);
        const ull* w2p = reinterpret_cast<const ull*>(cP.Wf + 64);
#pragma unroll
        for (int j = 0; j < 16; j++) {
            ull w0 = w0p[j], w1 = w1p[j], w2 = w2p[j];
#pragma unroll
            for (int q = 0; q < R; q++) {
                ull h = relu2(h2[q][j]);
                ax0[q] = ffma2(h, w0, ax0[q]);
                ax1[q] = ffma2(h, w1, ax1[q]);
                ax2[q] = ffma2(h, w2, ax2[q]);
            }
        }
#pragma unroll
        for (int q = 0; q < R; q++) {
            x0[q] = hadd2(ax0[q]); x1[q] = hadd2(ax1[q]); x2[q] = hadd2(ax2[q]);
        }
    }

    // ---- MAF flow: 10 layers; output stage dot-form ----
#pragma unroll 1
    for (int l = 0; l < 10; l++) {
        const float* fhx0 = cP.FhX0 + l * 32;
        const float* fhx1 = cP.FhX1 + l * 16;
        const float* fbh  = cP.Fbh  + l * 32;
        const ull* fmu2   = reinterpret_cast<const ull*>(cP.FoMu2 + l * 32);
        const ull* fal2   = reinterpret_cast<const ull*>(cP.FoAl2 + l * 32);
        const ull* fmu1   = reinterpret_cast<const ull*>(cP.FoMu1 + l * 16);
        const ull* fal1   = reinterpret_cast<const ull*>(cP.FoAl1 + l * 16);
        const float* fba  = cP.FbA + l * 8;
        const float* fb0  = cP.Fb0 + l * 2;

        ull x0b[R], x1b[R];
#pragma unroll
        for (int q = 0; q < R; q++) { x0b[q] = pk2(x0[q], x0[q]); x1b[q] = pk2(x1[q], x1[q]); }

        ull am1[R], aa1[R], am2[R], aa2[R];
        {
            const ulonglong2* pb = reinterpret_cast<const ulonglong2*>(fba);
            ulonglong2 v0 = pb[0], v1 = pb[1];
#pragma unroll
            for (int q = 0; q < R; q++) { am1[q] = v0.x; aa1[q] = v0.y; am2[q] = v1.x; aa2[q] = v1.y; }
        }

        // ---- block1: 16 deg-2 units (x0 + x1 inputs; feed mu2/al2 only) ----
        {
            ull hh[R][8];
            const ulonglong2* pbh = reinterpret_cast<const ulonglong2*>(fbh);
#pragma unroll
            for (int p = 0; p < 4; p++) {
                ulonglong2 v = pbh[p];
#pragma unroll
                for (int q = 0; q < R; q++) { hh[q][2 * p] = v.x; hh[q][2 * p + 1] = v.y; }
            }
            const ulonglong2* w0 = reinterpret_cast<const ulonglong2*>(fhx0);
            const ulonglong2* w1 = reinterpret_cast<const ulonglong2*>(fhx1);
#pragma unroll
            for (int p = 0; p < 4; p++) {
                ulonglong2 v = w0[p];
#pragma unroll
                for (int q = 0; q < R; q++) {
                    hh[q][2 * p]     = ffma2(x0b[q], v.x, hh[q][2 * p]);
                    hh[q][2 * p + 1] = ffma2(x0b[q], v.y, hh[q][2 * p + 1]);
                }
            }
#pragma unroll
            for (int p = 0; p < 4; p++) {
                ulonglong2 v = w1[p];
#pragma unroll
                for (int q = 0; q < R; q++) {
                    hh[q][2 * p]     = ffma2(x1b[q], v.x, hh[q][2 * p]);
                    hh[q][2 * p + 1] = ffma2(x1b[q], v.y, hh[q][2 * p + 1]);
                }
            }
#pragma unroll
            for (int p = 0; p < 8; p++) {
                ull wm2 = fmu2[p], wa2 = fal2[p];
#pragma unroll
                for (int q = 0; q < R; q++) {
                    ull h = relu2(hh[q][p]);
                    am2[q] = ffma2(h, wm2, am2[q]);
                    aa2[q] = ffma2(h, wa2, aa2[q]);
                }
            }
        }
        // ---- block2: 16 deg-1 units (x0 only; feed mu1/al1 AND mu2/al2) ----
        {
            ull hh[R][8];
            const ulonglong2* pbh = reinterpret_cast<const ulonglong2*>(fbh + 16);
#pragma unroll
            for (int p = 0; p < 4; p++) {
                ulonglong2 v = pbh[p];
#pragma unroll
                for (int q = 0; q < R; q++) { hh[q][2 * p] = v.x; hh[q][2 * p + 1] = v.y; }
            }
            const ulonglong2* w0 = reinterpret_cast<const ulonglong2*>(fhx0 + 16);
#pragma unroll
            for (int p = 0; p < 4; p++) {
                ulonglong2 v = w0[p];
#pragma unroll
                for (int q = 0; q < R; q++) {
                    hh[q][2 * p]     = ffma2(x0b[q], v.x, hh[q][2 * p]);
                    hh[q][2 * p + 1] = ffma2(x0b[q], v.y, hh[q][2 * p + 1]);
                }
            }
#pragma unroll
            for (int p = 0; p < 8; p++) {
                ull wm2 = fmu2[8 + p], wa2 = fal2[8 + p];
                ull wm1 = fmu1[p],     wa1 = fal1[p];
#pragma unroll
                for (int q = 0; q < R; q++) {
                    ull h = relu2(hh[q][p]);
                    am2[q] = ffma2(h, wm2, am2[q]);
                    aa2[q] = ffma2(h, wa2, aa2[q]);
                    am1[q] = ffma2(h, wm1, am1[q]);
                    aa1[q] = ffma2(h, wa1, aa1[q]);
                }
            }
        }

        float bmu0 = fb0[0], esc0 = fb0[1];
#pragma unroll
        for (int q = 0; q < R; q++) {
            float mu1 = hadd2(am1[q]), al1 = hadd2(aa1[q]);
            float mu2 = hadd2(am2[q]), al2 = hadd2(aa2[q]);
            float t1 = tanh_fast(al1);
            float t2 = tanh_fast(al2);
            float nx0 = (x0[q] - bmu0) * esc0;
            float nx1 = (x1[q] - mu1) * __expf(-t1);
            float nx2 = (x2[q] - mu2) * __expf(-t2);
            x0[q] = nx2; x1[q] = nx1; x2[q] = nx0;
        }
    }

    // ---- squash + HSV + store  (sigmoid(x) = 0.5*(1+tanh(x/2))) ----
#pragma unroll
    for (int q = 0; q < R; q++) {
        int rq = rbase + q * 128;
        if (rq < B) {
            float t0 = tanh_fast(0.5f * x0[q]);
            float t1 = tanh_fast(0.5f * x1[q]);
            float t2 = tanh_fast(0.5f * x2[q]);
            out[3 * rq + 0] = fmaf(3.14159265358979323846f, t0, 3.14159265358979323846f);
            out[3 * rq + 1] = fmaf(0.5f, t1, 0.5f);
            out[3 * rq + 2] = fmaf(0.5f, t2, 0.5f);
        }
    }
}

extern "C" void kernel_launch(void* const* d_in, const int* in_sizes, int n_in,
                              void* d_out, int out_size) {
    (void)n_in; (void)out_size;
    const float* states   = (const float*)d_in[0];
    const float* enc_w1   = (const float*)d_in[1];
    const float* enc_b1   = (const float*)d_in[2];
    const float* enc_w2   = (const float*)d_in[3];
    const float* enc_b2   = (const float*)d_in[4];
    const float* enc_w3   = (const float*)d_in[5];
    const float* enc_b3   = (const float*)d_in[6];
    const float* proj_w   = (const float*)d_in[7];
    const float* proj_b   = (const float*)d_in[8];
    const float* flow_wh  = (const float*)d_in[9];
    const float* flow_bh  = (const float*)d_in[10];
    const float* flow_wmu = (const float*)d_in[11];
    const float* flow_bmu = (const float*)d_in[12];
    const float* flow_wa  = (const float*)d_in[13];
    const float* flow_ba  = (const float*)d_in[14];

    // 1) bake folded/permuted weights into device staging
    bake_kernel<<<1, 128>>>(enc_w1, enc_b1, enc_w2, enc_b2, enc_w3, enc_b3,
                            proj_w, proj_b, flow_wh, flow_bh, flow_wmu, flow_bmu,
                            flow_wa, flow_ba);
    // 2) staging -> __constant__ (D2D async; graph-capturable, no allocation)
    void* stage_ptr = nullptr;
    cudaGetSymbolAddress(&stage_ptr, g_stage);
    cudaMemcpyToSymbolAsync(cP, stage_ptr, sizeof(CParams), 0,
                            cudaMemcpyDeviceToDevice, 0);
    // 3) main kernel reads weights through the const/LDCU uniform path
    const int B = in_sizes[0] / 4;
    const int grid = (B + 128 * R - 1) / (128 * R);
    gsi_kernel<<<grid, 128>>>(states, (float*)d_out, B);
}